// round 16
// baseline (speedup 1.0000x reference)
#include <cuda_runtime.h>

typedef unsigned long long u64;

#define NXg 256
#define NYg 256
#define NCELL (NXg*NYg)
#define TSTEPS 256
#define NSIG 2
#define TR 32            // tile rows (x)
#define TC 16            // tile cols (y)
#define EPP 28           // smem pitch: 2 left guard + 24 + 2 right guard
#define SROWS 42         // 1 top guard + 40 + 1 bottom guard
#define ROW0 1
#define COL0 2
#define NTH 480          // 15 warps; one 1x2-cell block per thread (40x12 blocks = 480)
#define BPR 12           // blocks per row
#define TILES_X 8
#define TILES_Y 16
#define NBS (TILES_X*TILES_Y)   // 128 CTAs per signal
#define NB (NSIG*NBS)           // 256 CTAs total (2/SM co-resident)

// Ping-pong magnetization state (only interior band cells ever written/read)
__device__ __align__(16) float g_state[2][NSIG][3*NCELL];
// per-tile monotonic step flags, one 32B sector each (zero-init; monotonic across replays)
__device__ unsigned g_done[NB*8];

// ---- packed f32x2 helpers ----
static __device__ __forceinline__ u64 pk2(float lo, float hi) {
    u64 r; asm("mov.b64 %0,{%1,%2};" : "=l"(r) : "f"(lo), "f"(hi)); return r;
}
static __device__ __forceinline__ void upk2(u64 v, float &lo, float &hi) {
    asm("mov.b64 {%0,%1}, %2;" : "=f"(lo), "=f"(hi) : "l"(v));
}
static __device__ __forceinline__ u64 f2add(u64 a, u64 b) {
    u64 r; asm("add.rn.f32x2 %0,%1,%2;" : "=l"(r) : "l"(a), "l"(b)); return r;
}
static __device__ __forceinline__ u64 f2mul(u64 a, u64 b) {
    u64 r; asm("mul.rn.f32x2 %0,%1,%2;" : "=l"(r) : "l"(a), "l"(b)); return r;
}
static __device__ __forceinline__ u64 f2fma(u64 a, u64 b, u64 c) {
    u64 r; asm("fma.rn.f32x2 %0,%1,%2,%3;" : "=l"(r) : "l"(a), "l"(b), "l"(c)); return r;
}
// ---- gpu-scope acquire/release flag ops ----
static __device__ __forceinline__ unsigned ld_acq(const unsigned* p) {
    unsigned v; asm volatile("ld.acquire.gpu.u32 %0,[%1];" : "=r"(v) : "l"(p) : "memory"); return v;
}
static __device__ __forceinline__ void st_rel(unsigned* p, unsigned v) {
    asm volatile("st.release.gpu.u32 [%0],%1;" :: "l"(p), "r"(v) : "memory");
}

__global__ __launch_bounds__(NTH, 2) void mm_persist_kernel(
    const float* __restrict__ sig,        // (NSIG, TSTEPS, 3)
    const float* __restrict__ Bext,       // (1,3,NX,NY)
    const float* __restrict__ Msat_p,     // scalar
    const int*   __restrict__ src_pos,    // (3,2)
    const int*   __restrict__ probe_pos,  // (5,2)
    float*       __restrict__ out)        // (NSIG, TSTEPS, 5)
{
    __shared__ __align__(16) float stg[2][3][SROWS*EPP];

    const int tid = threadIdx.x;
    const int bid = blockIdx.x;
    const int s    = bid / NBS;
    const int tile = bid % NBS;
    const int tx   = tile / TILES_Y;
    const int ty   = tile % TILES_Y;
    const int ti0  = tx * TR;
    const int tj0  = ty * TC;

    unsigned* myflag = &g_done[bid*8];
    const unsigned base = ld_acq(myflag);   // monotonic across graph replays

    // zero smem once (guard-ring hygiene)
    for (int i = tid; i < 2*3*SROWS*EPP; i += NTH)
        ((float*)stg)[i] = 0.0f;

    const float Msat  = Msat_p[0];
    const float cexch = 7.0e-12f / ((Msat * 5e-8f) * 5e-8f);
    const float cdem  = 1.2566371e-06f * Msat;
    const float alpha = 0.01f;
    const float pref  = -1.0f / (1.0f + alpha*alpha);

    const u64 C_M4   = pk2(-4.0f, -4.0f);
    const u64 C_EXCH = pk2(cexch, cexch);
    const u64 C_NDEM = pk2(-cdem, -cdem);
    const u64 C_NEG1 = pk2(-1.0f, -1.0f);
    const u64 C_PREF = pk2(pref, pref);
    const u64 C_ALPH = pk2(alpha, alpha);
    const u64 C_SOT  = pk2(1.0e-4f, 1.0e-4f);
    const u64 C_TWO  = pk2(2.0f, 2.0f);
    const u64 C_CH   = pk2(0.439875f, 0.439875f);       // 0.5*h
    const u64 C_HH   = pk2(0.87975f, 0.87975f);         // h
    const u64 C_H6   = pk2((float)(0.87975/6.0), (float)(0.87975/6.0));

    // one 1x2-cell block per thread: row br (0..39), col pair bc (0..11)
    const int  br  = tid / BPR;
    const int  bc  = tid - br*BPR;
    const int  gi0 = ti0 - 4 + br;
    const int  gj0 = tj0 - 4 + 2*bc;
    const bool ing = gi0 >= 0 && gi0 < NXg && gj0 >= 0 && gj0 <= NYg-2;
    const bool interior_blk = br >= 4 && br < 36 && bc >= 2 && bc < 10;
    const bool deep = br >= 8 && br < 32 && bc >= 4 && bc < 8;
    const bool band = interior_blk && !deep;
    const bool rim  = ing && !interior_blk;

    // rim block -> owning neighbor tile flag
    const unsigned* nflag = myflag;
    if (rim) {
        int drow = (br < 4) ? -1 : (br >= 36 ? 1 : 0);
        int dcol = (bc < 2) ? -1 : (bc >= 10 ? 1 : 0);
        nflag = &g_done[((s*TILES_X + tx + drow)*TILES_Y + ty + dcol)*8];
    }

    const int  B0  = (ROW0 + br)*EPP + (COL0 + 2*bc);   // even -> 8B aligned
    const bool clU = (gi0 == 0), clD = (gi0 == NXg-1);
    const bool clL = (gj0 == 0), clR = (gj0+1 == NYg-1);
    const int  iU  = clU ? B0 : B0 - EPP;     // up pair (LDS.64)
    const int  iD  = clD ? B0 : B0 + EPP;     // down pair (LDS.64)
    const int  iL  = clL ? B0 : B0 - 1;
    const int  iR  = clR ? B0 + 1 : B0 + 2;
    const int  g0  = gi0*NYg + gj0;

    // packed per-thread state: one f32x2 pair per component
    u64 MR[3], M[3], A[3];
    u64 BFX = 0, BFY = 0, BZ = 0, BZT = 0;
    MR[0] = 0; MR[1] = pk2(1.0f, 1.0f); MR[2] = 0;
    int srcf = 0, prf = 0;   // 4 bits per cell (2 cells)

    if (ing) {
        int sp[6], pp[10];
        #pragma unroll
        for (int k = 0; k < 6; k++)  sp[k] = src_pos[k];
        #pragma unroll
        for (int k = 0; k < 10; k++) pp[k] = probe_pos[k];
        float2 v;
        v = *(const float2*)&Bext[g0];          BFX = pk2(v.x, v.y);
        v = *(const float2*)&Bext[NCELL+g0];    BFY = pk2(v.x, v.y);
        v = *(const float2*)&Bext[2*NCELL+g0];  BZ  = pk2(v.x, v.y);
        #pragma unroll
        for (int c = 0; c < 2; c++) {
            int gj = gj0 + c;
            #pragma unroll
            for (int k = 0; k < 3; k++)
                if (gi0 == sp[2*k] && gj == sp[2*k+1]) srcf |= (k+1) << (4*c);
            #pragma unroll
            for (int p = 0; p < 5; p++)
                if (gi0 == pp[2*p] && gj == pp[2*p+1]) prf |= (p+1) << (4*c);
        }
    }

    // initial stg[0] fill (t=0 stage field)
    #pragma unroll
    for (int X = 0; X < 3; X++)
        *(u64*)&stg[0][X][B0] = MR[X];

    for (int t = 0; t < TSTEPS; t++) {
        const float* __restrict__ bin  = g_state[t & 1][s];
        float*       __restrict__ bout = g_state[(t & 1) ^ 1][s];

        // rim: wait for owning neighbor to finish step t-1, then pull its band (L2)
        if (rim && t > 0) {
            unsigned tgt = base + (unsigned)t;
            while ((int)(ld_acq(nflag) - tgt) < 0) { }
            MR[0] = __ldcg((const u64*)&bin[g0]);
            MR[1] = __ldcg((const u64*)&bin[NCELL+g0]);
            MR[2] = __ldcg((const u64*)&bin[2*NCELL+g0]);
            #pragma unroll
            for (int X = 0; X < 3; X++)
                *(u64*)&stg[0][X][B0] = MR[X];
        }

        if (srcf) {
            const float* sgp = &sig[(s*TSTEPS + t)*3];
            int k0 = srcf & 15, k1 = (srcf >> 4) & 15;
            float sa0 = k0 ? __ldg(&sgp[k0-1]) : 0.0f;
            float sa1 = k1 ? __ldg(&sgp[k1-1]) : 0.0f;
            BZT = f2add(BZ, pk2(sa0, sa1));
        } else {
            BZT = BZ;
        }
        #pragma unroll
        for (int X = 0; X < 3; X++) { M[X] = MR[X]; A[X] = 0; }
        __syncthreads();

        // One RK4 stage for all threads (guard-ring garbage never reaches interior).
#define MM_STAGE(CUR, NXT, WISONE, DO_NEXT, C2)                                     \
        {                                                                           \
            u64 LAP[3];                                                             \
            _Pragma("unroll")                                                       \
            for (int X = 0; X < 3; X++) {                                           \
                const float* Sp = stg[CUR][X];                                      \
                u64 U = *(const u64*)&Sp[iU];                                       \
                u64 D = *(const u64*)&Sp[iD];                                       \
                float l = Sp[iL], r = Sp[iR];                                       \
                float a0, a1; upk2(M[X], a0, a1);                                   \
                u64 h = f2add(pk2(l, a0), pk2(a1, r));                              \
                LAP[X] = f2fma(M[X], C_M4, f2add(f2add(U, D), h));                  \
            }                                                                       \
            u64 bx = f2fma(LAP[0], C_EXCH, BFX);                                    \
            u64 by = f2fma(LAP[1], C_EXCH, BFY);                                    \
            u64 bz = f2fma(M[2], C_NDEM, f2fma(LAP[2], C_EXCH, BZT));               \
            u64 n0 = f2mul(M[0], C_NEG1);                                           \
            u64 n1 = f2mul(M[1], C_NEG1);                                           \
            u64 n2 = f2mul(M[2], C_NEG1);                                           \
            u64 cx = f2fma(M[1], bz, f2mul(n2, by));                                \
            u64 cy = f2fma(M[2], bx, f2mul(n0, bz));                                \
            u64 cz = f2fma(M[0], by, f2mul(n1, bx));                                \
            u64 dx = f2fma(M[1], cz, f2mul(n2, cy));                                \
            u64 dy = f2fma(M[2], cx, f2mul(n0, cz));                                \
            u64 dz = f2fma(M[0], cy, f2mul(n1, cx));                                \
            u64 kx = f2fma(C_SOT, f2mul(M[1], M[0]),                                \
                           f2mul(C_PREF, f2fma(C_ALPH, dx, cx)));                   \
            u64 ky = f2fma(C_SOT, f2fma(n0, M[0], f2mul(n2, M[2])),                 \
                           f2mul(C_PREF, f2fma(C_ALPH, dy, cy)));                   \
            u64 kz = f2fma(C_SOT, f2mul(M[1], M[2]),                                \
                           f2mul(C_PREF, f2fma(C_ALPH, dz, cz)));                   \
            if (WISONE) {                                                           \
                A[0] = f2add(A[0], kx);                                             \
                A[1] = f2add(A[1], ky);                                             \
                A[2] = f2add(A[2], kz);                                             \
            } else {                                                                \
                A[0] = f2fma(kx, C_TWO, A[0]);                                      \
                A[1] = f2fma(ky, C_TWO, A[1]);                                      \
                A[2] = f2fma(kz, C_TWO, A[2]);                                      \
            }                                                                       \
            if (DO_NEXT) {                                                          \
                M[0] = f2fma(kx, C2, MR[0]);                                        \
                M[1] = f2fma(ky, C2, MR[1]);                                        \
                M[2] = f2fma(kz, C2, MR[2]);                                        \
                *(u64*)&stg[NXT][0][B0] = M[0];                                     \
                *(u64*)&stg[NXT][1][B0] = M[1];                                     \
                *(u64*)&stg[NXT][2][B0] = M[2];                                     \
                __syncthreads();                                                    \
            }                                                                       \
        }

        MM_STAGE(0, 1, true,  true,  C_CH)   // k1 -> m + 0.5h k1
        MM_STAGE(1, 0, false, true,  C_CH)   // k2 -> m + 0.5h k2
        MM_STAGE(0, 1, false, true,  C_HH)   // k3 -> m + h   k3
        MM_STAGE(1, 0, true,  false, C_CH)   // k4 (reads stg[1] only; no sync)
#undef MM_STAGE

        // combine; interior stays in regs; stg[0] pre-filled for next step
        if (interior_blk) {
            #pragma unroll
            for (int X = 0; X < 3; X++) {
                MR[X] = f2fma(A[X], C_H6, MR[X]);
                *(u64*)&stg[0][X][B0] = MR[X];
            }
            if (band) {
                __stcg((u64*)&bout[g0],           MR[0]);
                __stcg((u64*)&bout[NCELL+g0],     MR[1]);
                __stcg((u64*)&bout[2*NCELL+g0],   MR[2]);
            }
            if (prf) {
                float z0, z1; upk2(MR[2], z0, z1);
                int p0 = prf & 15, p1 = (prf >> 4) & 15;
                if (p0) out[(s*TSTEPS + t)*5 + (p0-1)] = z0;
                if (p1) out[(s*TSTEPS + t)*5 + (p1-1)] = z1;
            }
        }

        // post completion of step t (release after band stores)
        __syncthreads();
        if (tid == 0) {
            __threadfence();
            st_rel(myflag, base + (unsigned)(t + 1));
        }
    }
}

extern "C" void kernel_launch(void* const* d_in, const int* in_sizes, int n_in,
                              void* d_out, int out_size) {
    const float* sig       = (const float*)d_in[0];  // (2,256,3)
    const float* Bext      = (const float*)d_in[1];  // (1,3,256,256)
    const float* Msat      = (const float*)d_in[2];  // scalar
    const int*   src_pos   = (const int*)d_in[3];    // (3,2)
    const int*   probe_pos = (const int*)d_in[4];    // (5,2)
    float*       out       = (float*)d_out;          // (2,256,5)

    mm_persist_kernel<<<NB, NTH>>>(sig, Bext, Msat, src_pos, probe_pos, out);
}